// round 4
// baseline (speedup 1.0000x reference)
#include <cuda_runtime.h>

// ---------------- problem constants ----------------
#define IMG_H 512
#define IMG_W 512
#define OUT_H 502           // 512 - 11 + 1
#define OUT_W 502
#define NCHAN 96            // B*C = 32*3
#define NPIX_TOTAL 24192384.0   // 96 * 502 * 502

// ---------------- tile geometry ----------------
#define OW_T 32             // outputs per tile (x)
#define OH_T 51             // outputs per tile (y)
#define IW_T 42             // OW_T + 10
#define IH_T 61             // OH_T + 10
#define S_STRIDE 43         // odd stride -> conflict-free LDS for input tiles
#define H_STRIDE 33         // odd stride -> conflict-free LDS/STS for intermediates
#define NTHREADS 256
#define GRID_X 16           // ceil(502/32)
#define GRID_Y 10           // ceil(502/51)
#define NBLOCKS (GRID_X * GRID_Y * NCHAN)   // 15360

#define C1_CONST 1.0e-4f    // 0.01^2
#define C2_CONST 9.0e-4f    // 0.03^2

// Gaussian window (sigma=1.5, 11 taps), normalized. constexpr so weights fold
// into FFMA src1-immediates (imm form 0x823, rt_SMSP=1 -> full fp32 rate).
__device__ __forceinline__ constexpr float wt(int k) {
    return (k == 0 || k == 10) ? 0.00102838f
         : (k == 1 || k == 9)  ? 0.00759876f
         : (k == 2 || k == 8)  ? 0.03600077f
         : (k == 3 || k == 7)  ? 0.10936069f
         : (k == 4 || k == 6)  ? 0.21300554f
         :                       0.26601171f;
}

__device__ double g_accum;          // zero-initialized at module load; each
__device__ unsigned int g_count;    // launch leaves both back at zero.

__global__ void __launch_bounds__(NTHREADS, 2)
ssim_main_kernel(const float* __restrict__ img1, const float* __restrict__ img2,
                 float* __restrict__ out) {
    extern __shared__ float smem[];
    float* s1 = smem;                          // IH_T * S_STRIDE
    float* s2 = s1 + IH_T * S_STRIDE;          // IH_T * S_STRIDE
    float* hb = s2 + IH_T * S_STRIDE;          // 5 * IH_T * H_STRIDE
    __shared__ float red[NTHREADS];
    __shared__ int s_is_last;

    const int tid = threadIdx.x;
    const int x0g = blockIdx.x * OW_T;
    const int y0g = blockIdx.y * OH_T;
    const size_t base = (size_t)blockIdx.z * (IMG_H * IMG_W);

    // ---------------- Phase A: load input tiles (zero-fill OOB) ----------------
    for (int i = tid; i < IH_T * IW_T; i += NTHREADS) {
        int r = i / IW_T;
        int c = i - r * IW_T;
        int gy = y0g + r;
        int gx = x0g + c;
        float a = 0.0f, b = 0.0f;
        if (gy < IMG_H && gx < IMG_W) {
            size_t idx = base + (size_t)gy * IMG_W + gx;
            a = img1[idx];
            b = img2[idx];
        }
        s1[r * S_STRIDE + c] = a;
        s2[r * S_STRIDE + c] = b;
    }
    __syncthreads();

    // ---------------- Phase B: horizontal separable conv ----------------
    // Exactly 61 rows x 4 x-strips (8 outputs each) = 244 tasks, single pass.
    if (tid < IH_T * 4) {
        const int r  = tid >> 2;
        const int xs = (tid & 3) * 8;
        float acc[5][8];
        #pragma unroll
        for (int f = 0; f < 5; f++)
            #pragma unroll
            for (int o = 0; o < 8; o++) acc[f][o] = 0.0f;

        const float* p1 = s1 + r * S_STRIDE + xs;
        const float* p2 = s2 + r * S_STRIDE + xs;
        #pragma unroll
        for (int i = 0; i < 18; i++) {
            float a = p1[i];
            float b = p2[i];
            float aa = a * a;
            float bb = b * b;
            float ab = a * b;
            #pragma unroll
            for (int o = 0; o < 8; o++) {
                const int k = i - o;
                if (k >= 0 && k < 11) {
                    const float w = wt(k);
                    acc[0][o] += w * a;
                    acc[1][o] += w * b;
                    acc[2][o] += w * aa;
                    acc[3][o] += w * bb;
                    acc[4][o] += w * ab;
                }
            }
        }
        #pragma unroll
        for (int f = 0; f < 5; f++) {
            float* hp = hb + f * (IH_T * H_STRIDE) + r * H_STRIDE + xs;
            #pragma unroll
            for (int o = 0; o < 8; o++) hp[o] = acc[f][o];
        }
    }
    __syncthreads();

    // ---------------- Phase C: vertical conv + SSIM ----------------
    // Thread = (x = tid&31, warp strip of 7 output rows). 8 warps x 7 = 56 >= 51.
    float local = 0.0f;
    {
        const int x  = tid & 31;
        const int ys = (tid >> 5) * 7;
        float acc[5][7];
        #pragma unroll
        for (int f = 0; f < 5; f++)
            #pragma unroll
            for (int o = 0; o < 7; o++) acc[f][o] = 0.0f;

        #pragma unroll
        for (int i = 0; i < 17; i++) {
            // Clamp row for warp 7: rows >= IH_T would only feed outputs
            // >= OH_T, which the output guard below discards.
            const int r = min(ys + i, IH_T - 1);
            float v0 = hb[0 * (IH_T * H_STRIDE) + r * H_STRIDE + x];
            float v1 = hb[1 * (IH_T * H_STRIDE) + r * H_STRIDE + x];
            float v2 = hb[2 * (IH_T * H_STRIDE) + r * H_STRIDE + x];
            float v3 = hb[3 * (IH_T * H_STRIDE) + r * H_STRIDE + x];
            float v4 = hb[4 * (IH_T * H_STRIDE) + r * H_STRIDE + x];
            #pragma unroll
            for (int o = 0; o < 7; o++) {
                const int k = i - o;
                if (k >= 0 && k < 11) {
                    const float w = wt(k);
                    acc[0][o] += w * v0;
                    acc[1][o] += w * v1;
                    acc[2][o] += w * v2;
                    acc[3][o] += w * v3;
                    acc[4][o] += w * v4;
                }
            }
        }

        const int gx = x0g + x;
        if (gx < OUT_W) {
            #pragma unroll
            for (int o = 0; o < 7; o++) {
                const int oy = ys + o;
                const int gy = y0g + oy;
                if (oy < OH_T && gy < OUT_H) {
                    float mu1 = acc[0][o];
                    float mu2 = acc[1][o];
                    float m11 = mu1 * mu1;
                    float m22 = mu2 * mu2;
                    float m12 = mu1 * mu2;
                    float sg1 = acc[2][o] - m11;
                    float sg2 = acc[3][o] - m22;
                    float s12 = acc[4][o] - m12;
                    float num = (2.0f * m12 + C1_CONST) * (2.0f * s12 + C2_CONST);
                    float den = (m11 + m22 + C1_CONST) * (sg1 + sg2 + C2_CONST);
                    local += __fdividef(num, den);
                }
            }
        }
    }

    // ---------------- block reduce ----------------
    red[tid] = local;
    __syncthreads();
    #pragma unroll
    for (int s = NTHREADS / 2; s > 0; s >>= 1) {
        if (tid < s) red[tid] += red[tid + s];
        __syncthreads();
    }

    // ---------------- global accumulate + last-block finalize ----------------
    if (tid == 0) {
        atomicAdd(&g_accum, (double)red[0]);
        __threadfence();
        unsigned int t = atomicAdd(&g_count, 1u);
        s_is_last = (t == (unsigned int)(NBLOCKS - 1)) ? 1 : 0;
    }
    __syncthreads();
    if (s_is_last && tid == 0) {
        double total = atomicAdd(&g_accum, 0.0);   // coherent read
        out[0] = (float)(total * (1.0 / NPIX_TOTAL));
        g_accum = 0.0;          // reset for the next graph replay
        g_count = 0u;
        __threadfence();
    }
}

extern "C" void kernel_launch(void* const* d_in, const int* in_sizes, int n_in,
                              void* d_out, int out_size) {
    const float* img1 = (const float*)d_in[0];
    const float* img2 = (const float*)d_in[1];
    float* out = (float*)d_out;

    const size_t smem_bytes =
        (size_t)(2 * IH_T * S_STRIDE + 5 * IH_T * H_STRIDE) * sizeof(float); // ~59.8 KB
    cudaFuncSetAttribute(ssim_main_kernel,
                         cudaFuncAttributeMaxDynamicSharedMemorySize,
                         (int)smem_bytes);

    dim3 grid(GRID_X, GRID_Y, NCHAN);   // 16 x 10 x 96 = 15360
    ssim_main_kernel<<<grid, NTHREADS, smem_bytes>>>(img1, img2, out);
}

// round 5
// speedup vs baseline: 1.0405x; 1.0405x over previous
#include <cuda_runtime.h>

// ---------------- problem constants ----------------
#define IMG_H 512
#define IMG_W 512
#define OUT_H 502           // 512 - 11 + 1
#define OUT_W 502
#define NCHAN 96            // B*C = 32*3
#define NPIX_TOTAL 24192384.0   // 96 * 502 * 502

// ---------------- tile geometry ----------------
#define OW_T 32             // outputs per tile (x)
#define OH_T 64             // outputs per tile (y)
#define IW_T 42             // OW_T + 10
#define IH_T 74             // OH_T + 10
#define S_STRIDE 43         // odd stride -> conflict-free 32-bit LDS
#define H_STRIDE 33         // row stride (in float2 for hbA/hbB, float for hbC)
#define NTHREADS 256
#define GRID_X 16           // ceil(502/32)
#define GRID_Y 8            // ceil(502/64)
#define NBLOCKS (GRID_X * GRID_Y * NCHAN)   // 12288

#define C1_CONST 1.0e-4f    // 0.01^2
#define C2_CONST 9.0e-4f    // 0.03^2

// smem layout (floats). hbA first => 8B alignment for float2 accesses.
#define HBA_OFF 0                               // 74*33 float2 = 4884 floats
#define HBB_OFF (IH_T * H_STRIDE * 2)           // 4884 floats
#define HBC_OFF (HBB_OFF + IH_T * H_STRIDE * 2) // 2442 floats
#define S1_OFF  (HBC_OFF + IH_T * H_STRIDE)
#define S2_OFF  (S1_OFF + IH_T * S_STRIDE)
#define SMEM_FLOATS (S2_OFF + IH_T * S_STRIDE)  // 18574 floats = 74296 B

// Gaussian window (sigma=1.5, 11 taps), normalized; constexpr so taps fold
// into FFMA src1-immediates (imm form, rt_SMSP=1).
__device__ __forceinline__ constexpr float wt(int k) {
    return (k == 0 || k == 10) ? 0.00102838f
         : (k == 1 || k == 9)  ? 0.00759876f
         : (k == 2 || k == 8)  ? 0.03600077f
         : (k == 3 || k == 7)  ? 0.10936069f
         : (k == 4 || k == 6)  ? 0.21300554f
         :                       0.26601171f;
}

__device__ double g_accum;          // zero-initialized at module load; the
__device__ unsigned int g_count;    // kernel leaves both back at zero.

__global__ void __launch_bounds__(NTHREADS, 3)
ssim_main_kernel(const float* __restrict__ img1, const float* __restrict__ img2,
                 float* __restrict__ out) {
    extern __shared__ float smem[];
    float2* hbA = (float2*)(smem + HBA_OFF);   // fields (mu1, mu2)
    float2* hbB = (float2*)(smem + HBB_OFF);   // fields (x*x, y*y)
    float*  hbC = smem + HBC_OFF;              // field  (x*y)
    float*  s1  = smem + S1_OFF;
    float*  s2  = smem + S2_OFF;
    __shared__ float red[8];
    __shared__ int s_is_last;

    const int tid = threadIdx.x;
    const int lane = tid & 31;
    const int warp = tid >> 5;
    const int x0g = blockIdx.x * OW_T;
    const int y0g = blockIdx.y * OH_T;
    const size_t base = (size_t)blockIdx.z * (IMG_H * IMG_W);

    // ---------------- Phase A: load input tiles (zero-fill OOB) --------------
    for (int i = tid; i < IH_T * IW_T; i += NTHREADS) {
        int r = i / IW_T;
        int c = i - r * IW_T;
        int gy = y0g + r;
        int gx = x0g + c;
        float a = 0.0f, b = 0.0f;
        if (gy < IMG_H && gx < IMG_W) {
            size_t idx = base + (size_t)gy * IMG_W + gx;
            a = img1[idx];
            b = img2[idx];
        }
        s1[r * S_STRIDE + c] = a;
        s2[r * S_STRIDE + c] = b;
    }
    __syncthreads();

    // ---------------- Phase B: horizontal separable conv ---------------------
    // 74 rows x 4 strips (8 outputs) = 296 tasks over 256 threads (2 passes,
    // 40 straggler tasks; occ=3 CTAs hides the tail).
    for (int t = tid; t < IH_T * 4; t += NTHREADS) {
        const int r  = t >> 2;
        const int xs = (t & 3) * 8;
        float acc[5][8];
        #pragma unroll
        for (int f = 0; f < 5; f++)
            #pragma unroll
            for (int o = 0; o < 8; o++) acc[f][o] = 0.0f;

        const float* p1 = s1 + r * S_STRIDE + xs;
        const float* p2 = s2 + r * S_STRIDE + xs;
        #pragma unroll
        for (int i = 0; i < 18; i++) {
            float a = p1[i];
            float b = p2[i];
            float aa = a * a;
            float bb = b * b;
            float ab = a * b;
            #pragma unroll
            for (int o = 0; o < 8; o++) {
                const int k = i - o;
                if (k >= 0 && k < 11) {
                    const float w = wt(k);
                    acc[0][o] += w * a;
                    acc[1][o] += w * b;
                    acc[2][o] += w * aa;
                    acc[3][o] += w * bb;
                    acc[4][o] += w * ab;
                }
            }
        }
        const int hbase = r * H_STRIDE + xs;
        #pragma unroll
        for (int o = 0; o < 8; o++) {
            hbA[hbase + o] = make_float2(acc[0][o], acc[1][o]);
            hbB[hbase + o] = make_float2(acc[2][o], acc[3][o]);
            hbC[hbase + o] = acc[4][o];
        }
    }
    __syncthreads();

    // ---------------- Phase C: vertical conv + SSIM --------------------------
    // Thread = (x = lane, warp strip of 8 output rows). 8 warps x 8 = 64 rows.
    // Rows read: ys..ys+17, max 56+17 = 73 < IH_T -> no clamp needed.
    float local = 0.0f;
    {
        const int x  = lane;
        const int ys = warp * 8;
        float a01[2][8], a23[2][8], a4[8];
        #pragma unroll
        for (int o = 0; o < 8; o++) {
            a01[0][o] = 0.0f; a01[1][o] = 0.0f;
            a23[0][o] = 0.0f; a23[1][o] = 0.0f;
            a4[o] = 0.0f;
        }

        const int cb = ys * H_STRIDE + x;
        #pragma unroll
        for (int i = 0; i < 18; i++) {
            const int idx = cb + i * H_STRIDE;
            float2 v01 = hbA[idx];
            float2 v23 = hbB[idx];
            float  v4  = hbC[idx];
            #pragma unroll
            for (int o = 0; o < 8; o++) {
                const int k = i - o;
                if (k >= 0 && k < 11) {
                    const float w = wt(k);
                    a01[0][o] += w * v01.x;
                    a01[1][o] += w * v01.y;
                    a23[0][o] += w * v23.x;
                    a23[1][o] += w * v23.y;
                    a4[o]     += w * v4;
                }
            }
        }

        const int gx = x0g + x;
        if (gx < OUT_W) {
            #pragma unroll
            for (int o = 0; o < 8; o++) {
                const int gy = y0g + ys + o;
                if (gy < OUT_H) {
                    float mu1 = a01[0][o];
                    float mu2 = a01[1][o];
                    float m11 = mu1 * mu1;
                    float m22 = mu2 * mu2;
                    float m12 = mu1 * mu2;
                    float sg1 = a23[0][o] - m11;
                    float sg2 = a23[1][o] - m22;
                    float s12 = a4[o] - m12;
                    float num = (2.0f * m12 + C1_CONST) * (2.0f * s12 + C2_CONST);
                    float den = (m11 + m22 + C1_CONST) * (sg1 + sg2 + C2_CONST);
                    local += __fdividef(num, den);
                }
            }
        }
    }

    // ---------------- reduce: warp shuffle, then cross-warp ------------------
    #pragma unroll
    for (int s = 16; s > 0; s >>= 1)
        local += __shfl_xor_sync(0xFFFFFFFFu, local, s);
    if (lane == 0) red[warp] = local;
    __syncthreads();
    if (warp == 0) {
        float v = (lane < 8) ? red[lane] : 0.0f;
        #pragma unroll
        for (int s = 4; s > 0; s >>= 1)
            v += __shfl_xor_sync(0xFFFFFFFFu, v, s);
        if (lane == 0) {
            atomicAdd(&g_accum, (double)v);
            __threadfence();
            unsigned int t = atomicAdd(&g_count, 1u);
            s_is_last = (t == (unsigned int)(NBLOCKS - 1)) ? 1 : 0;
        }
    }
    __syncthreads();
    if (s_is_last && tid == 0) {
        double total = atomicAdd(&g_accum, 0.0);   // coherent read
        out[0] = (float)(total * (1.0 / NPIX_TOTAL));
        g_accum = 0.0;          // reset for next graph replay
        g_count = 0u;
        __threadfence();
    }
}

extern "C" void kernel_launch(void* const* d_in, const int* in_sizes, int n_in,
                              void* d_out, int out_size) {
    const float* img1 = (const float*)d_in[0];
    const float* img2 = (const float*)d_in[1];
    float* out = (float*)d_out;

    const size_t smem_bytes = (size_t)SMEM_FLOATS * sizeof(float); // 74296 B
    cudaFuncSetAttribute(ssim_main_kernel,
                         cudaFuncAttributeMaxDynamicSharedMemorySize,
                         (int)smem_bytes);

    dim3 grid(GRID_X, GRID_Y, NCHAN);   // 16 x 8 x 96 = 12288
    ssim_main_kernel<<<grid, NTHREADS, smem_bytes>>>(img1, img2, out);
}

// round 6
// speedup vs baseline: 1.5074x; 1.4487x over previous
#include <cuda_runtime.h>

// ---------------- problem constants ----------------
#define IMG_H 512
#define IMG_W 512
#define OUT_H 502           // 512 - 11 + 1
#define OUT_W 502
#define NCHAN 96            // B*C = 32*3
#define NPIX_TOTAL 24192384.0   // 96 * 502 * 502

// ---------------- tile geometry ----------------
#define OW_T 32             // outputs per tile (x)
#define OH_T 54             // outputs per tile (y)
#define IW_T 42             // OW_T + 10
#define IH_T 64             // OH_T + 10  -> Phase B = 64 rows * 4 strips = 256 tasks
#define H_STRIDE 33         // hb row stride (in elements)
#define NTHREADS 256
#define GRID_X 16           // ceil(502/32)
#define GRID_Y 10           // ceil(502/54)
#define NBLOCKS (GRID_X * GRID_Y * NCHAN)   // 15360

#define C1_CONST 1.0e-4f    // 0.01^2
#define C2_CONST 9.0e-4f    // 0.03^2

// smem: hbA (mu1,mu2 pairs), hbB (x2,y2 pairs) as 64-bit, hbC (xy) scalar.
// 64*33*8*2 + 64*33*4 = 42240 B  ->  4 CTAs/SM (reg-capped), smem allows 5.
#define HB_ELEMS (IH_T * H_STRIDE)

typedef unsigned long long u64;

__device__ __forceinline__ u64 pack2(float x, float y) {
    u64 r; asm("mov.b64 %0, {%1,%2};" : "=l"(r) : "f"(x), "f"(y)); return r;
}
__device__ __forceinline__ void unpack2(u64 v, float& x, float& y) {
    asm("mov.b64 {%0,%1}, %2;" : "=f"(x), "=f"(y) : "l"(v));
}
// d = a*b + d   (packed 2x fp32 MAC, one issue slot)
__device__ __forceinline__ void ffma2(u64& d, u64 a, u64 b) {
    asm("fma.rn.f32x2 %0, %1, %2, %0;" : "+l"(d) : "l"(a), "l"(b));
}
__device__ __forceinline__ u64 fmul2(u64 a, u64 b) {
    u64 r; asm("mul.rn.f32x2 %0, %1, %2;" : "=l"(r) : "l"(a), "l"(b)); return r;
}

// Gaussian window (sigma=1.5, 11 taps), normalized; symmetric -> 6 distinct.
__device__ __forceinline__ constexpr float wt(int k) {
    return (k == 0 || k == 10) ? 0.00102838f
         : (k == 1 || k == 9)  ? 0.00759876f
         : (k == 2 || k == 8)  ? 0.03600077f
         : (k == 3 || k == 7)  ? 0.10936069f
         : (k == 4 || k == 6)  ? 0.21300554f
         :                       0.26601171f;
}
#define WIDX(k) ((k) < 6 ? (k) : 10 - (k))

__device__ double g_accum;          // zero at module load; kernel leaves both
__device__ unsigned int g_count;    // back at zero after each replay.

__global__ void __launch_bounds__(NTHREADS, 4)
ssim_main_kernel(const float* __restrict__ img1, const float* __restrict__ img2,
                 float* __restrict__ out) {
    extern __shared__ float smem[];
    u64*   hbA = (u64*)smem;                       // (mu1, mu2)
    u64*   hbB = hbA + HB_ELEMS;                   // (x*x, y*y)
    float* hbC = (float*)(hbB + HB_ELEMS);         // x*y
    __shared__ float red[8];
    __shared__ int s_is_last;

    const int tid  = threadIdx.x;
    const int lane = tid & 31;
    const int warp = tid >> 5;
    const int x0g  = blockIdx.x * OW_T;
    const int y0g  = blockIdx.y * OH_T;
    const size_t base = (size_t)blockIdx.z * (IMG_H * IMG_W);

    // Packed (w,w) weight registers, 6 distinct taps.
    u64 W2[6];
    #pragma unroll
    for (int k = 0; k < 6; k++) W2[k] = pack2(wt(k), wt(k));

    // ---------------- Phase B: horizontal conv, global -> smem ---------------
    // Exactly 256 tasks: row r = tid>>2 (64 rows), strip xs = (tid&3)*8.
    // Addresses are CLAMPED, not zero-filled: clamp garbage only feeds
    // h-columns >= 22 of the right-edge tile / rows beyond the image, all of
    // which map to outputs >= OUT_W / OUT_H that the epilogue guard discards.
    {
        const int r  = tid >> 2;
        const int xs = (tid & 3) * 8;
        const int gy = min(y0g + r, IMG_H - 1);
        const float* p1 = img1 + base + (size_t)gy * IMG_W;
        const float* p2 = img2 + base + (size_t)gy * IMG_W;

        u64 accP1[8], accP2[8];
        float acc3[8];
        #pragma unroll
        for (int o = 0; o < 8; o++) { accP1[o] = 0; accP2[o] = 0; acc3[o] = 0.0f; }

        #pragma unroll
        for (int i = 0; i < 18; i++) {
            const int c = min(x0g + xs + i, IMG_W - 1);
            float a = __ldg(p1 + c);
            float b = __ldg(p2 + c);
            u64 pab = pack2(a, b);
            u64 paa = fmul2(pab, pab);
            float ab = a * b;
            #pragma unroll
            for (int o = 0; o < 8; o++) {
                const int k = i - o;
                if (k >= 0 && k < 11) {
                    ffma2(accP1[o], pab, W2[WIDX(k)]);
                    ffma2(accP2[o], paa, W2[WIDX(k)]);
                    acc3[o] += wt(k) * ab;     // imm-form FFMA
                }
            }
        }
        const int hbase = r * H_STRIDE + xs;
        #pragma unroll
        for (int o = 0; o < 8; o++) {
            hbA[hbase + o] = accP1[o];
            hbB[hbase + o] = accP2[o];
            hbC[hbase + o] = acc3[o];
        }
    }
    __syncthreads();

    // ---------------- Phase C: vertical conv + SSIM --------------------------
    // Thread = (x = lane, warp strip of 7 output rows); 8*7 = 56 >= 54.
    // Row clamp (min) only affects outputs oy >= 54, discarded below.
    float local = 0.0f;
    {
        const int x  = lane;
        const int ys = warp * 7;
        u64 acc01[7], acc23[7];
        float a4[7];
        #pragma unroll
        for (int o = 0; o < 7; o++) { acc01[o] = 0; acc23[o] = 0; a4[o] = 0.0f; }

        #pragma unroll
        for (int i = 0; i < 17; i++) {
            const int r = min(ys + i, IH_T - 1);
            const int idx = r * H_STRIDE + x;
            u64 v01 = hbA[idx];
            u64 v23 = hbB[idx];
            float v4 = hbC[idx];
            #pragma unroll
            for (int o = 0; o < 7; o++) {
                const int k = i - o;
                if (k >= 0 && k < 11) {
                    ffma2(acc01[o], v01, W2[WIDX(k)]);
                    ffma2(acc23[o], v23, W2[WIDX(k)]);
                    a4[o] += wt(k) * v4;       // imm-form FFMA
                }
            }
        }

        const int gx = x0g + x;
        if (gx < OUT_W) {
            #pragma unroll
            for (int o = 0; o < 7; o++) {
                const int oy = ys + o;
                const int gy = y0g + oy;
                if (oy < OH_T && gy < OUT_H) {
                    float mu1, mu2, ex2, ey2;
                    unpack2(acc01[o], mu1, mu2);
                    unpack2(acc23[o], ex2, ey2);
                    float m11 = mu1 * mu1;
                    float m22 = mu2 * mu2;
                    float m12 = mu1 * mu2;
                    float sg1 = ex2 - m11;
                    float sg2 = ey2 - m22;
                    float s12 = a4[o] - m12;
                    float num = (2.0f * m12 + C1_CONST) * (2.0f * s12 + C2_CONST);
                    float den = (m11 + m22 + C1_CONST) * (sg1 + sg2 + C2_CONST);
                    local += __fdividef(num, den);
                }
            }
        }
    }

    // ---------------- reduce: warp shuffle, then cross-warp ------------------
    #pragma unroll
    for (int s = 16; s > 0; s >>= 1)
        local += __shfl_xor_sync(0xFFFFFFFFu, local, s);
    if (lane == 0) red[warp] = local;
    __syncthreads();
    if (warp == 0) {
        float v = (lane < 8) ? red[lane] : 0.0f;
        #pragma unroll
        for (int s = 4; s > 0; s >>= 1)
            v += __shfl_xor_sync(0xFFFFFFFFu, v, s);
        if (lane == 0) {
            atomicAdd(&g_accum, (double)v);
            __threadfence();
            unsigned int t = atomicAdd(&g_count, 1u);
            s_is_last = (t == (unsigned int)(NBLOCKS - 1)) ? 1 : 0;
        }
    }
    __syncthreads();
    if (s_is_last && tid == 0) {
        double total = atomicAdd(&g_accum, 0.0);   // coherent read
        out[0] = (float)(total * (1.0 / NPIX_TOTAL));
        g_accum = 0.0;          // reset for next graph replay
        g_count = 0u;
        __threadfence();
    }
}

extern "C" void kernel_launch(void* const* d_in, const int* in_sizes, int n_in,
                              void* d_out, int out_size) {
    const float* img1 = (const float*)d_in[0];
    const float* img2 = (const float*)d_in[1];
    float* out = (float*)d_out;

    const size_t smem_bytes = (size_t)HB_ELEMS * 20;   // 2*u64 + 1*f32 = 42240 B
    cudaFuncSetAttribute(ssim_main_kernel,
                         cudaFuncAttributeMaxDynamicSharedMemorySize,
                         (int)smem_bytes);

    dim3 grid(GRID_X, GRID_Y, NCHAN);   // 16 x 10 x 96 = 15360
    ssim_main_kernel<<<grid, NTHREADS, smem_bytes>>>(img1, img2, out);
}

// round 7
// speedup vs baseline: 2.1736x; 1.4420x over previous
#include <cuda_runtime.h>

// ---------------- problem constants ----------------
#define IMG_H 512
#define IMG_W 512
#define OUT_H 502           // 512 - 11 + 1
#define OUT_W 502
#define NCHAN 96            // B*C = 32*3
#define NPIX_TOTAL 24192384.0   // 96 * 502 * 502

// ---------------- tile geometry ----------------
#define OW_T 32             // outputs per tile (x)
#define OH_T 54             // outputs per tile (y)
#define IH_T 64             // OH_T + 10  -> Phase B = 64 rows * 4 strips = 256 tasks
#define H_STRIDE 33         // hb row stride (in elements)
#define NTHREADS 256
#define GRID_X 16           // ceil(502/32)
#define GRID_Y 10           // ceil(502/54)
#define NBLOCKS (GRID_X * GRID_Y * NCHAN)   // 15360

#define C1_CONST 1.0e-4f    // 0.01^2
#define C2_CONST 9.0e-4f    // 0.03^2

#define HB_ELEMS (IH_T * H_STRIDE)

typedef unsigned long long u64;

__device__ __forceinline__ u64 pack2(float x, float y) {
    u64 r; asm("mov.b64 %0, {%1,%2};" : "=l"(r) : "f"(x), "f"(y)); return r;
}
__device__ __forceinline__ void unpack2(u64 v, float& x, float& y) {
    asm("mov.b64 {%0,%1}, %2;" : "=f"(x), "=f"(y) : "l"(v));
}
// d = a*b + d   (packed 2x fp32 MAC, one issue slot)
__device__ __forceinline__ void ffma2(u64& d, u64 a, u64 b) {
    asm("fma.rn.f32x2 %0, %1, %2, %0;" : "+l"(d) : "l"(a), "l"(b));
}
__device__ __forceinline__ u64 fmul2(u64 a, u64 b) {
    u64 r; asm("mul.rn.f32x2 %0, %1, %2;" : "=l"(r) : "l"(a), "l"(b)); return r;
}

// Gaussian window (sigma=1.5, 11 taps), normalized; symmetric -> 6 distinct.
__device__ __forceinline__ constexpr float wt(int k) {
    return (k == 0 || k == 10) ? 0.00102838f
         : (k == 1 || k == 9)  ? 0.00759876f
         : (k == 2 || k == 8)  ? 0.03600077f
         : (k == 3 || k == 7)  ? 0.10936069f
         : (k == 4 || k == 6)  ? 0.21300554f
         :                       0.26601171f;
}
#define WIDX(k) ((k) < 6 ? (k) : 10 - (k))

__device__ double g_accum;          // zero at module load; kernel leaves both
__device__ unsigned int g_count;    // back at zero after each replay.

__global__ void __launch_bounds__(NTHREADS, 4)
ssim_main_kernel(const float* __restrict__ img1, const float* __restrict__ img2,
                 float* __restrict__ out) {
    extern __shared__ float smem[];
    u64*   hbA = (u64*)smem;                       // (mu1, mu2)
    u64*   hbB = hbA + HB_ELEMS;                   // (x*x, y*y)
    float* hbC = (float*)(hbB + HB_ELEMS);         // x*y
    __shared__ float red[8];
    __shared__ int s_is_last;

    const int tid  = threadIdx.x;
    const int lane = tid & 31;
    const int warp = tid >> 5;
    const int x0g  = blockIdx.x * OW_T;
    const int y0g  = blockIdx.y * OH_T;
    const size_t base = (size_t)blockIdx.z * (IMG_H * IMG_W);

    // Packed (w,w) weight registers, 6 distinct taps.
    u64 W2[6];
    #pragma unroll
    for (int k = 0; k < 6; k++) W2[k] = pack2(wt(k), wt(k));

    // ---------------- Phase B: horizontal conv, global -> smem ---------------
    // Exactly 256 tasks: row r = tid>>2, strip xs = (tid&3)*8.
    // Vectorized LDG.128: 5 float4 per image per thread from 16B-aligned
    // addresses. Row pointer clamped to the last row; each float4's start
    // clamped to IMG_W-4. Vertical conv consumes the SAME column, so h col c
    // feeds only output col c; all clamp-garbage lands in h cols >= 22 /
    // rows >= 26 of edge tiles, which the epilogue guard discards.
    {
        const int r  = tid >> 2;
        const int xs = (tid & 3) * 8;
        const int gy = min(y0g + r, IMG_H - 1);
        const float* p1 = img1 + base + (size_t)gy * IMG_W;
        const float* p2 = img2 + base + (size_t)gy * IMG_W;

        u64 accP1[8], accP2[8];
        float acc3[8];
        #pragma unroll
        for (int o = 0; o < 8; o++) { accP1[o] = 0; accP2[o] = 0; acc3[o] = 0.0f; }

        const int bx = x0g + xs;
        #pragma unroll
        for (int j = 0; j < 5; j++) {
            const int c = min(bx + 4 * j, IMG_W - 4);
            const float4 va = *reinterpret_cast<const float4*>(p1 + c);
            const float4 vb = *reinterpret_cast<const float4*>(p2 + c);
            const float A[4] = {va.x, va.y, va.z, va.w};
            const float B[4] = {vb.x, vb.y, vb.z, vb.w};
            #pragma unroll
            for (int t = 0; t < 4; t++) {
                const int i = 4 * j + t;
                if (i < 18) {
                    u64 pab = pack2(A[t], B[t]);
                    u64 paa = fmul2(pab, pab);
                    float ab = A[t] * B[t];
                    #pragma unroll
                    for (int o = 0; o < 8; o++) {
                        const int k = i - o;
                        if (k >= 0 && k < 11) {
                            ffma2(accP1[o], pab, W2[WIDX(k)]);
                            ffma2(accP2[o], paa, W2[WIDX(k)]);
                            acc3[o] += wt(k) * ab;     // imm-form FFMA
                        }
                    }
                }
            }
        }
        const int hbase = r * H_STRIDE + xs;
        #pragma unroll
        for (int o = 0; o < 8; o++) {
            hbA[hbase + o] = accP1[o];
            hbB[hbase + o] = accP2[o];
            hbC[hbase + o] = acc3[o];
        }
    }
    __syncthreads();

    // ---------------- Phase C: vertical conv + SSIM --------------------------
    // Thread = (x = lane, warp strip of 7 output rows); 8*7 = 56 >= 54.
    // Row clamp (min) only affects outputs oy >= 54, discarded below.
    float local = 0.0f;
    {
        const int x  = lane;
        const int ys = warp * 7;
        u64 acc01[7], acc23[7];
        float a4[7];
        #pragma unroll
        for (int o = 0; o < 7; o++) { acc01[o] = 0; acc23[o] = 0; a4[o] = 0.0f; }

        #pragma unroll
        for (int i = 0; i < 17; i++) {
            const int r = min(ys + i, IH_T - 1);
            const int idx = r * H_STRIDE + x;
            u64 v01 = hbA[idx];
            u64 v23 = hbB[idx];
            float v4 = hbC[idx];
            #pragma unroll
            for (int o = 0; o < 7; o++) {
                const int k = i - o;
                if (k >= 0 && k < 11) {
                    ffma2(acc01[o], v01, W2[WIDX(k)]);
                    ffma2(acc23[o], v23, W2[WIDX(k)]);
                    a4[o] += wt(k) * v4;       // imm-form FFMA
                }
            }
        }

        const int gx = x0g + x;
        if (gx < OUT_W) {
            #pragma unroll
            for (int o = 0; o < 7; o++) {
                const int oy = ys + o;
                const int gy = y0g + oy;
                if (oy < OH_T && gy < OUT_H) {
                    float mu1, mu2, ex2, ey2;
                    unpack2(acc01[o], mu1, mu2);
                    unpack2(acc23[o], ex2, ey2);
                    float m11 = mu1 * mu1;
                    float m22 = mu2 * mu2;
                    float m12 = mu1 * mu2;
                    float sg1 = ex2 - m11;
                    float sg2 = ey2 - m22;
                    float s12 = a4[o] - m12;
                    float num = (2.0f * m12 + C1_CONST) * (2.0f * s12 + C2_CONST);
                    float den = (m11 + m22 + C1_CONST) * (sg1 + sg2 + C2_CONST);
                    local += __fdividef(num, den);
                }
            }
        }
    }

    // ---------------- reduce: warp shuffle, then cross-warp ------------------
    #pragma unroll
    for (int s = 16; s > 0; s >>= 1)
        local += __shfl_xor_sync(0xFFFFFFFFu, local, s);
    if (lane == 0) red[warp] = local;
    __syncthreads();
    if (warp == 0) {
        float v = (lane < 8) ? red[lane] : 0.0f;
        #pragma unroll
        for (int s = 4; s > 0; s >>= 1)
            v += __shfl_xor_sync(0xFFFFFFFFu, v, s);
        if (lane == 0) {
            atomicAdd(&g_accum, (double)v);
            __threadfence();
            unsigned int t = atomicAdd(&g_count, 1u);
            s_is_last = (t == (unsigned int)(NBLOCKS - 1)) ? 1 : 0;
        }
    }
    __syncthreads();
    if (s_is_last && tid == 0) {
        double total = atomicAdd(&g_accum, 0.0);   // coherent read
        out[0] = (float)(total * (1.0 / NPIX_TOTAL));
        g_accum = 0.0;          // reset for next graph replay
        g_count = 0u;
        __threadfence();
    }
}

extern "C" void kernel_launch(void* const* d_in, const int* in_sizes, int n_in,
                              void* d_out, int out_size) {
    const float* img1 = (const float*)d_in[0];
    const float* img2 = (const float*)d_in[1];
    float* out = (float*)d_out;

    const size_t smem_bytes = (size_t)HB_ELEMS * 20;   // 2*u64 + 1*f32 = 42240 B
    cudaFuncSetAttribute(ssim_main_kernel,
                         cudaFuncAttributeMaxDynamicSharedMemorySize,
                         (int)smem_bytes);

    dim3 grid(GRID_X, GRID_Y, NCHAN);   // 16 x 10 x 96 = 15360
    ssim_main_kernel<<<grid, NTHREADS, smem_bytes>>>(img1, img2, out);
}